// round 14
// baseline (speedup 1.0000x reference)
#include <cuda_runtime.h>
#include <math.h>

#define HH    1024
#define SS    512
#define OO    512
#define LL    3
#define NPAIR 32            // 64 batches as 32 packed pairs
#define NBLK  128
#define NTHR  512
#define SMEM_BYTES 184320   // 64K sh_t + 64K sh_h + 48K red + 2K sh_z + 2K sh_gx

typedef unsigned long long ull;

// ---------------- device scratch (static; no runtime allocation) ----------------
__device__ __align__(16) float4 g_WA  [LL * HH * HH];       // [l][k][c] = (Wxz,Whz,Wxr,Whr)[c][k]
__device__ __align__(16) float4 g_WxG4[LL * (HH/4) * HH];   // [l][k4][c] = Wxg[c][4k4..+3]
__device__ __align__(16) float4 g_WhG4[LL * (HH/4) * HH];   // [l][k4][c] = Whg[c][4k4..+3]
__device__ __align__(16) float4 g_WO4 [(HH/4) * OO];        // [k4][o]   = Wo[o][4k4..+3]
__device__ __align__(16) float2 g_h   [LL * NPAIR * HH];    // hidden, pair-packed [l][p][k]
__device__ __align__(16) float2 g_rh  [NPAIR * HH];         // r*h scratch (cross-block)
__device__ __align__(16) float2 g_h2  [(long)SS * NPAIR * HH]; // last-layer h history [s][p][k]
__device__ unsigned g_barcnt;

// ---------------- packed f32x2 helpers ----------------
__device__ __forceinline__ ull splat2(float a) {
    ull r; asm("mov.b64 %0, {%1, %1};" : "=l"(r) : "f"(a)); return r;
}
__device__ __forceinline__ float2 up2(ull v) {
    float2 r; asm("mov.b64 {%0, %1}, %2;" : "=f"(r.x), "=f"(r.y) : "l"(v)); return r;
}
__device__ __forceinline__ void fma2(ull &d, ull a, ull b) {
    asm("fma.rn.f32x2 %0, %1, %2, %0;" : "+l"(d) : "l"(a), "l"(b));
}
__device__ __forceinline__ ull add2(ull a, ull b) {
    ull r; asm("add.rn.f32x2 %0, %1, %2;" : "=l"(r) : "l"(a), "l"(b)); return r;
}

// ---------------- grid barrier (128 co-resident blocks) ----------------
// ALL threads fence (publish their global stores to L2) before the counter bump.
__device__ __forceinline__ void gsync(unsigned target) {
    __threadfence();
    __syncthreads();
    if (threadIdx.x == 0) {
        unsigned v = atomicAdd(&g_barcnt, 1u) + 1u;
        while (v < target) v = atomicAdd(&g_barcnt, 0u);   // atomic read: fresh L2 value
    }
    __syncthreads();
}

// ---------------- packing kernels ----------------
__global__ void pack_main(const float* __restrict__ Wxz, const float* __restrict__ Whz,
                          const float* __restrict__ Wxr, const float* __restrict__ Whr) {
    int idx = blockIdx.x * blockDim.x + threadIdx.x;
    if (idx >= LL * HH * HH) return;
    int c = idx & 1023, k = (idx >> 10) & 1023, l = idx >> 20;
    int src = (l * HH + c) * HH + k;
    g_WA[idx] = make_float4(Wxz[src], Whz[src], Wxr[src], Whr[src]);
}
__global__ void pack_g4(const float* __restrict__ Wxg, const float* __restrict__ Whg) {
    int idx = blockIdx.x * blockDim.x + threadIdx.x;
    if (idx >= LL * (HH/4) * HH) return;
    int c = idx & 1023, k4 = (idx >> 10) & 255, l = idx >> 18;
    int src = (l * HH + c) * HH + 4 * k4;
    g_WxG4[idx] = *(const float4*)(Wxg + src);
    g_WhG4[idx] = *(const float4*)(Whg + src);
}
__global__ void pack_o(const float* __restrict__ Wo) {
    int idx = blockIdx.x * blockDim.x + threadIdx.x;
    if (idx >= (HH/4) * OO) return;
    int o = idx & 511, k4 = idx >> 9;
    g_WO4[idx] = *(const float4*)(Wo + o * HH + 4 * k4);
}
__global__ void init_h(const float* __restrict__ h0) {
    int idx = blockIdx.x * blockDim.x + threadIdx.x;
    if (idx == 0) g_barcnt = 0u;
    if (idx >= LL * NPAIR * HH) return;
    int k = idx & 1023, p = (idx >> 10) & 31, l = idx >> 15;
    g_h[(l * NPAIR + p) * HH + k] =
        make_float2(h0[(2*p*LL + l) * HH + k], h0[((2*p+1)*LL + l) * HH + k]);
}

// ---------------- persistent GRU recurrence ----------------
// 128 blocks = 32 column-blocks (32 cols each) x 4 batch-groups (16 batches = 8 pairs).
// 512 threads = 32 cols x 16 k-segments (64 k each).
__global__ void __launch_bounds__(NTHR, 1) gru_persist(
    const float* __restrict__ x,
    const float* __restrict__ bhz, const float* __restrict__ bhr,
    const float* __restrict__ bhg)
{
    extern __shared__ char smem[];
    float2* sh_t  = (float2*)(smem);             // [8][1024] pair-packed t_in
    float2* sh_h  = (float2*)(smem + 65536);     // [8][1024] pair-packed h
    ull*    red   = (ull*)   (smem + 131072);    // [8 slots][24][32]
    float2* sh_z  = (float2*)(smem + 180224);    // [8][32]
    float2* sh_gx = (float2*)(smem + 182272);    // [8][32]

    const int tid  = threadIdx.x;
    const int c    = tid & 31;
    const int kseg = tid >> 5;
    const int C0   = (blockIdx.x & 31) * 32;
    const int P0   = (blockIdx.x >> 5) * 8;
    const int C    = C0 + c;
    unsigned target = 0;

    for (int s = 0; s < SS; s++) {
        for (int l = 0; l < LL; l++) {
            // ======== phase A: z, r, x-side of g ========
            {
                const float2* hsrc = g_h + (l * NPAIR + P0) * HH;
                const float2* tsrc = (l > 0) ? (g_h + ((l-1) * NPAIR + P0) * HH) : (const float2*)0;
                for (int i = tid; i < 8192; i += NTHR) {
                    int arr = i >> 12;
                    int p   = (i >> 9) & 7;
                    int k2  = (i & 511) << 1;
                    if (arr) {
                        *(float4*)(sh_h + p * HH + k2) = __ldcg((const float4*)(hsrc + p * HH + k2));
                    } else if (l == 0) {
                        float2 a = __ldcg((const float2*)(x + ((long)(2*(P0+p))   * SS + s) * HH + k2));
                        float2 b = __ldcg((const float2*)(x + ((long)(2*(P0+p)+1) * SS + s) * HH + k2));
                        *(float4*)(sh_t + p * HH + k2) = make_float4(a.x, b.x, a.y, b.y);
                    } else {
                        *(float4*)(sh_t + p * HH + k2) = __ldcg((const float4*)(tsrc + p * HH + k2));
                    }
                }
            }
            __syncthreads();

            ull az[8], ar[8], ag[8];
#pragma unroll
            for (int p = 0; p < 8; p++) { az[p] = 0; ar[p] = 0; ag[p] = 0; }
            {
                const float4* WA = g_WA   + l * (HH * HH);
                const float4* WX = g_WxG4 + l * ((HH/4) * HH);
                const int kend = (kseg + 1) << 6;
                for (int k = kseg << 6; k < kend; k += 4) {
                    float4 w0 = WA[(k+0) * HH + C];
                    float4 w1 = WA[(k+1) * HH + C];
                    float4 w2 = WA[(k+2) * HH + C];
                    float4 w3 = WA[(k+3) * HH + C];
                    ull xz0 = splat2(w0.x), hz0 = splat2(w0.y), xr0 = splat2(w0.z), hr0 = splat2(w0.w);
                    ull xz1 = splat2(w1.x), hz1 = splat2(w1.y), xr1 = splat2(w1.z), hr1 = splat2(w1.w);
                    ull xz2 = splat2(w2.x), hz2 = splat2(w2.y), xr2 = splat2(w2.z), hr2 = splat2(w2.w);
                    ull xz3 = splat2(w3.x), hz3 = splat2(w3.y), xr3 = splat2(w3.z), hr3 = splat2(w3.w);
#pragma unroll
                    for (int p = 0; p < 8; p++) {
                        ulonglong2 t01 = *(const ulonglong2*)(sh_t + p * HH + k);
                        ulonglong2 t23 = *(const ulonglong2*)(sh_t + p * HH + k + 2);
                        ulonglong2 h01 = *(const ulonglong2*)(sh_h + p * HH + k);
                        ulonglong2 h23 = *(const ulonglong2*)(sh_h + p * HH + k + 2);
                        fma2(az[p], t01.x, xz0); fma2(az[p], h01.x, hz0);
                        fma2(az[p], t01.y, xz1); fma2(az[p], h01.y, hz1);
                        fma2(az[p], t23.x, xz2); fma2(az[p], h23.x, hz2);
                        fma2(az[p], t23.y, xz3); fma2(az[p], h23.y, hz3);
                        fma2(ar[p], t01.x, xr0); fma2(ar[p], h01.x, hr0);
                        fma2(ar[p], t01.y, xr1); fma2(ar[p], h01.y, hr1);
                        fma2(ar[p], t23.x, xr2); fma2(ar[p], h23.x, hr2);
                        fma2(ar[p], t23.y, xr3); fma2(ar[p], h23.y, hr3);
                    }
                    float4 wg = WX[(k >> 2) * HH + C];
                    ull sg0 = splat2(wg.x), sg1 = splat2(wg.y), sg2 = splat2(wg.z), sg3 = splat2(wg.w);
#pragma unroll
                    for (int p = 0; p < 8; p++) {
                        ulonglong2 t01 = *(const ulonglong2*)(sh_t + p * HH + k);
                        ulonglong2 t23 = *(const ulonglong2*)(sh_t + p * HH + k + 2);
                        fma2(ag[p], t01.x, sg0); fma2(ag[p], t01.y, sg1);
                        fma2(ag[p], t23.x, sg2); fma2(ag[p], t23.y, sg3);
                    }
                }
            }
            __syncthreads();
            // reduce over 16 k-segments: fold 8..15 onto 0..7, then tree
            if (kseg >= 8) {
                int sl = kseg - 8;
#pragma unroll
                for (int p = 0; p < 8; p++) {
                    red[(sl*24 +      p) * 32 + c] = az[p];
                    red[(sl*24 +  8 + p) * 32 + c] = ar[p];
                    red[(sl*24 + 16 + p) * 32 + c] = ag[p];
                }
            }
            __syncthreads();
            if (kseg < 8) {
#pragma unroll
                for (int p = 0; p < 8; p++) {
                    red[(kseg*24 +      p)*32 + c] = add2(red[(kseg*24 +      p)*32 + c], az[p]);
                    red[(kseg*24 +  8 + p)*32 + c] = add2(red[(kseg*24 +  8 + p)*32 + c], ar[p]);
                    red[(kseg*24 + 16 + p)*32 + c] = add2(red[(kseg*24 + 16 + p)*32 + c], ag[p]);
                }
            }
            __syncthreads();
            for (int off = 4; off >= 1; off >>= 1) {
                if (kseg < off) {
                    for (int a = 0; a < 24; a++)
                        red[(kseg*24 + a)*32 + c] =
                            add2(red[(kseg*24 + a)*32 + c], red[((kseg+off)*24 + a)*32 + c]);
                }
                __syncthreads();
            }
            // epilogue: 512 threads cover all 24 result arrays.
            // a = tid>>5 in [0,16): a<8 -> z AND gx (arrays a and 16+a); a in [8,16) -> r.
            {
                int a  = tid >> 5;
                int cc = tid & 31;
                int Cg = C0 + cc;
                if (a < 8) {
                    int p = a;
                    float2 f = up2(red[a * 32 + cc]);
                    float bz = bhz[l * HH + Cg];
                    sh_z[p * 32 + cc] = make_float2(1.f/(1.f+expf(-(f.x+bz))),
                                                    1.f/(1.f+expf(-(f.y+bz))));
                    sh_gx[p * 32 + cc] = up2(red[(16 + p) * 32 + cc]);
                } else {
                    int p = a - 8;
                    float2 f = up2(red[a * 32 + cc]);
                    float br = bhr[l * HH + Cg];
                    float r0 = 1.f/(1.f+expf(-(f.x+br)));
                    float r1 = 1.f/(1.f+expf(-(f.y+br)));
                    float2 hv = sh_h[p * HH + Cg];
                    g_rh[(P0+p) * HH + Cg] = make_float2(r0*hv.x, r1*hv.y);
                }
            }
            target += NBLK; gsync(target);

            // ======== phase B: (r*h) @ Whg^T + update ========
            {
                const float2* rsrc = g_rh + P0 * HH;
                for (int i = tid; i < 4096; i += NTHR) {
                    int p  = i >> 9;
                    int k2 = (i & 511) << 1;
                    *(float4*)(sh_t + p * HH + k2) = __ldcg((const float4*)(rsrc + p * HH + k2));
                }
            }
            __syncthreads();
            ull ab[8];
#pragma unroll
            for (int p = 0; p < 8; p++) ab[p] = 0;
            {
                const float4* WH = g_WhG4 + l * ((HH/4) * HH);
                const int k4end = (kseg + 1) << 4;
                for (int k4 = kseg << 4; k4 < k4end; k4++) {
                    float4 w = WH[k4 * HH + C];
                    ull s0 = splat2(w.x), s1 = splat2(w.y), s2 = splat2(w.z), s3 = splat2(w.w);
                    int k = k4 << 2;
#pragma unroll
                    for (int p = 0; p < 8; p++) {
                        ulonglong2 t01 = *(const ulonglong2*)(sh_t + p * HH + k);
                        ulonglong2 t23 = *(const ulonglong2*)(sh_t + p * HH + k + 2);
                        fma2(ab[p], t01.x, s0); fma2(ab[p], t01.y, s1);
                        fma2(ab[p], t23.x, s2); fma2(ab[p], t23.y, s3);
                    }
                }
            }
            __syncthreads();
            if (kseg >= 8) {
                int sl = kseg - 8;
#pragma unroll
                for (int p = 0; p < 8; p++) red[(sl*8 + p)*32 + c] = ab[p];
            }
            __syncthreads();
            if (kseg < 8) {
#pragma unroll
                for (int p = 0; p < 8; p++)
                    red[(kseg*8 + p)*32 + c] = add2(red[(kseg*8 + p)*32 + c], ab[p]);
            }
            __syncthreads();
            for (int off = 4; off >= 1; off >>= 1) {
                if (kseg < off) {
                    for (int a = 0; a < 8; a++)
                        red[(kseg*8 + a)*32 + c] =
                            add2(red[(kseg*8 + a)*32 + c], red[((kseg+off)*8 + a)*32 + c]);
                }
                __syncthreads();
            }
            if (tid < 256) {
                int p = tid >> 5, cc = tid & 31;
                int Cg = C0 + cc;
                float2 f  = up2(red[p * 32 + cc]);
                float2 gx = sh_gx[p * 32 + cc];
                float  bg = bhg[l * HH + Cg];
                float g0 = tanhf(f.x + gx.x + bg);
                float g1 = tanhf(f.y + gx.y + bg);
                float2 zz = sh_z[p * 32 + cc];
                float2 hh = __ldcg((const float2*)&g_h[(l * NPAIR + P0 + p) * HH + Cg]);
                float hn0 = zz.x * hh.x + (1.f - zz.x) * g0;
                float hn1 = zz.y * hh.y + (1.f - zz.y) * g1;
                g_h[(l * NPAIR + P0 + p) * HH + Cg] = make_float2(hn0, hn1);
                if (l == 2)
                    g_h2[((long)s * NPAIR + P0 + p) * HH + Cg] = make_float2(hn0, hn1);
            }
            target += NBLK; gsync(target);
        }
    }
}

// ---------------- hidden-state output (B, L, H) ----------------
__global__ void copy_hidden(float* __restrict__ out2) {
    int idx = blockIdx.x * blockDim.x + threadIdx.x;
    if (idx >= LL * 64 * HH) return;
    int k = idx & 1023, b = (idx >> 10) & 63, l = idx >> 16;
    float2 v = g_h[(l * NPAIR + (b >> 1)) * HH + k];
    out2[(b * LL + l) * HH + k] = (b & 1) ? v.y : v.x;
}

// ---------------- output projection ----------------
// grid (8, 4096): 64 o-cols x 4 pair-rows per block; 256 threads = 64 o x 4 row-slots.
__global__ void __launch_bounds__(256) outGemm(const float* __restrict__ bo, float* __restrict__ out) {
    __shared__ __align__(16) float2 sh[4 * HH];
    int tid   = threadIdx.x;
    int o     = blockIdx.x * 64 + (tid & 63);
    int rslot = tid >> 6;
    long r0   = (long)blockIdx.y * 4;

    for (int i = tid; i < 2048; i += 256) {
        int rr = i >> 9;
        int k2 = (i & 511) << 1;
        *(float4*)(sh + rr * HH + k2) = *(const float4*)(g_h2 + (r0 + rr) * HH + k2);
    }
    __syncthreads();

    ull acc = 0;
    const float2* row = sh + rslot * HH;
    for (int k4 = 0; k4 < 256; k4++) {
        float4 w = g_WO4[k4 * OO + o];
        ull s0 = splat2(w.x), s1 = splat2(w.y), s2 = splat2(w.z), s3 = splat2(w.w);
        int k = k4 << 2;
        ulonglong2 t01 = *(const ulonglong2*)(row + k);
        ulonglong2 t23 = *(const ulonglong2*)(row + k + 2);
        fma2(acc, t01.x, s0); fma2(acc, t01.y, s1);
        fma2(acc, t23.x, s2); fma2(acc, t23.y, s3);
    }
    float2 f = up2(acc);
    long pr  = r0 + rslot;
    int sidx = (int)(pr >> 5);
    int p    = (int)(pr & 31);
    float bv = bo[o];
    out[((long)(2*p)     * SS + sidx) * OO + o] = f.x + bv;
    out[((long)(2*p + 1) * SS + sidx) * OO + o] = f.y + bv;
}

// ---------------- launch (7 graph nodes) ----------------
extern "C" void kernel_launch(void* const* d_in, const int* in_sizes, int n_in,
                              void* d_out, int out_size) {
    const float* x   = (const float*)d_in[0];
    const float* h0  = (const float*)d_in[1];
    const float* Wxz = (const float*)d_in[2];
    const float* Wxr = (const float*)d_in[3];
    const float* Wxg = (const float*)d_in[4];
    const float* Whz = (const float*)d_in[5];
    const float* Whr = (const float*)d_in[6];
    const float* Whg = (const float*)d_in[7];
    const float* bhz = (const float*)d_in[8];
    const float* bhr = (const float*)d_in[9];
    const float* bhg = (const float*)d_in[10];
    const float* Wo  = (const float*)d_in[11];
    const float* bo  = (const float*)d_in[12];
    float* out = (float*)d_out;

    static int smem_set = 0;
    if (!smem_set) {
        cudaFuncSetAttribute(gru_persist, cudaFuncAttributeMaxDynamicSharedMemorySize, SMEM_BYTES);
        smem_set = 1;
    }

    pack_main<<<(LL * HH * HH + 255) / 256, 256>>>(Wxz, Whz, Wxr, Whr);
    pack_g4  <<<(LL * (HH/4) * HH + 255) / 256, 256>>>(Wxg, Whg);
    pack_o   <<<((HH/4) * OO + 255) / 256, 256>>>(Wo);
    init_h   <<<(LL * NPAIR * HH + 255) / 256, 256>>>(h0);

    gru_persist<<<NBLK, NTHR, SMEM_BYTES>>>(x, bhz, bhr, bhg);

    copy_hidden<<<(LL * 64 * HH + 255) / 256, 256>>>(out + (long)64 * SS * OO);
    outGemm<<<dim3(8, (SS * NPAIR) / 4), 256>>>(bo, out);
}

// round 15
// speedup vs baseline: 1.0312x; 1.0312x over previous
#include <cuda_runtime.h>
#include <math.h>

#define HH    1024
#define SS    512
#define OO    512
#define LL    3
#define NPAIR 32            // 64 batches as 32 packed pairs
#define NBLK  128
#define NTHR  512
#define SMEM_BYTES 165888   // 64K sh_t + 64K sh_h + 32K red + 2K sh_z

typedef unsigned long long ull;

// ---------------- device scratch (static; no runtime allocation) ----------------
__device__ __align__(16) float4 g_WA  [LL * HH * HH];       // [l][k][c] = (Wxz,Whz,Wxr,Whr)[c][k]
__device__ __align__(16) float4 g_WxG4[LL * (HH/4) * HH];   // [l][k4][c] = Wxg[c][4k4..+3]
__device__ __align__(16) float4 g_WhG4[LL * (HH/4) * HH];   // [l][k4][c] = Whg[c][4k4..+3]
__device__ __align__(16) float4 g_WO4 [(HH/4) * OO];        // [k4][o]   = Wo[o][4k4..+3]
__device__ __align__(16) float2 g_h   [LL * NPAIR * HH];    // hidden, pair-packed [l][p][k]
__device__ __align__(16) float2 g_rh  [NPAIR * HH];         // r*h scratch (cross-block)
__device__ __align__(16) float2 g_h2  [(long)SS * NPAIR * HH]; // last-layer h history [s][p][k]
__device__ unsigned g_barcnt;

// ---------------- packed f32x2 helpers ----------------
__device__ __forceinline__ ull splat2(float a) {
    ull r; asm("mov.b64 %0, {%1, %1};" : "=l"(r) : "f"(a)); return r;
}
__device__ __forceinline__ float2 up2(ull v) {
    float2 r; asm("mov.b64 {%0, %1}, %2;" : "=f"(r.x), "=f"(r.y) : "l"(v)); return r;
}
__device__ __forceinline__ void fma2(ull &d, ull a, ull b) {
    asm("fma.rn.f32x2 %0, %1, %2, %0;" : "+l"(d) : "l"(a), "l"(b));
}
__device__ __forceinline__ ull add2(ull a, ull b) {
    ull r; asm("add.rn.f32x2 %0, %1, %2;" : "=l"(r) : "l"(a), "l"(b)); return r;
}

// ---------------- grid barrier (128 co-resident blocks) ----------------
// All threads fence (publish stores to L2), one thread bumps the counter with an
// atomic, then spins on an ACQUIRE LOAD (no atomic-unit serialization from pollers).
__device__ __forceinline__ void gsync(unsigned target) {
    __threadfence();
    __syncthreads();
    if (threadIdx.x == 0) {
        atomicAdd(&g_barcnt, 1u);
        unsigned v;
        do {
            asm volatile("ld.acquire.gpu.u32 %0, [%1];" : "=r"(v) : "l"(&g_barcnt) : "memory");
        } while (v < target);
    }
    __syncthreads();
}

// ---------------- packing kernels ----------------
__global__ void pack_main(const float* __restrict__ Wxz, const float* __restrict__ Whz,
                          const float* __restrict__ Wxr, const float* __restrict__ Whr) {
    int idx = blockIdx.x * blockDim.x + threadIdx.x;
    if (idx >= LL * HH * HH) return;
    int c = idx & 1023, k = (idx >> 10) & 1023, l = idx >> 20;
    int src = (l * HH + c) * HH + k;
    g_WA[idx] = make_float4(Wxz[src], Whz[src], Wxr[src], Whr[src]);
}
__global__ void pack_g4(const float* __restrict__ Wxg, const float* __restrict__ Whg) {
    int idx = blockIdx.x * blockDim.x + threadIdx.x;
    if (idx >= LL * (HH/4) * HH) return;
    int c = idx & 1023, k4 = (idx >> 10) & 255, l = idx >> 18;
    int src = (l * HH + c) * HH + 4 * k4;
    g_WxG4[idx] = *(const float4*)(Wxg + src);
    g_WhG4[idx] = *(const float4*)(Whg + src);
}
__global__ void pack_o(const float* __restrict__ Wo) {
    int idx = blockIdx.x * blockDim.x + threadIdx.x;
    if (idx >= (HH/4) * OO) return;
    int o = idx & 511, k4 = idx >> 9;
    g_WO4[idx] = *(const float4*)(Wo + o * HH + 4 * k4);
}
__global__ void init_h(const float* __restrict__ h0) {
    int idx = blockIdx.x * blockDim.x + threadIdx.x;
    if (idx == 0) g_barcnt = 0u;
    if (idx >= LL * NPAIR * HH) return;
    int k = idx & 1023, p = (idx >> 10) & 31, l = idx >> 15;
    g_h[(l * NPAIR + p) * HH + k] =
        make_float2(h0[(2*p*LL + l) * HH + k], h0[((2*p+1)*LL + l) * HH + k]);
}

// ---------------- persistent GRU recurrence ----------------
// 128 blocks = 32 column-blocks (32 cols each) x 4 batch-groups (16 batches = 8 pairs).
// 512 threads = 32 cols x 16 k-segments (64 k each).
// Phase A: z, r (4 weight streams). Phase B: g = x@Wxg + (r*h)@Whg (2 streams) + update.
__global__ void __launch_bounds__(NTHR, 1) gru_persist(
    const float* __restrict__ x,
    const float* __restrict__ bhz, const float* __restrict__ bhr,
    const float* __restrict__ bhg)
{
    extern __shared__ char smem[];
    float2* sh_t = (float2*)(smem);             // [8][1024] pair-packed t_in (lives through A+B)
    float2* sh_h = (float2*)(smem + 65536);     // [8][1024] h in phase A, r*h in phase B
    ull*    red  = (ull*)   (smem + 131072);    // [8 slots][16][32]
    float2* sh_z = (float2*)(smem + 163840);    // [8][32]

    const int tid  = threadIdx.x;
    const int c    = tid & 31;
    const int kseg = tid >> 5;
    const int C0   = (blockIdx.x & 31) * 32;
    const int P0   = (blockIdx.x >> 5) * 8;
    const int C    = C0 + c;
    unsigned target = 0;

    // epilogue threads cache their h element per layer (avoids a dependent L2 load)
    float2 h0r, h1r, h2r;
    if (tid < 256) {
        int p = tid >> 5, cc = tid & 31;
        h0r = g_h[(0 * NPAIR + P0 + p) * HH + C0 + cc];
        h1r = g_h[(1 * NPAIR + P0 + p) * HH + C0 + cc];
        h2r = g_h[(2 * NPAIR + P0 + p) * HH + C0 + cc];
    }

    for (int s = 0; s < SS; s++) {
        for (int l = 0; l < LL; l++) {
            // ======== phase A: z and r ========
            {
                const float2* hsrc = g_h + (l * NPAIR + P0) * HH;
                const float2* tsrc = (l > 0) ? (g_h + ((l-1) * NPAIR + P0) * HH) : (const float2*)0;
                for (int i = tid; i < 8192; i += NTHR) {
                    int arr = i >> 12;
                    int p   = (i >> 9) & 7;
                    int k2  = (i & 511) << 1;
                    if (arr) {
                        *(float4*)(sh_h + p * HH + k2) = __ldcg((const float4*)(hsrc + p * HH + k2));
                    } else if (l == 0) {
                        float2 a = __ldcg((const float2*)(x + ((long)(2*(P0+p))   * SS + s) * HH + k2));
                        float2 b = __ldcg((const float2*)(x + ((long)(2*(P0+p)+1) * SS + s) * HH + k2));
                        *(float4*)(sh_t + p * HH + k2) = make_float4(a.x, b.x, a.y, b.y);
                    } else {
                        *(float4*)(sh_t + p * HH + k2) = __ldcg((const float4*)(tsrc + p * HH + k2));
                    }
                }
            }
            __syncthreads();

            ull az[8], ar[8];
#pragma unroll
            for (int p = 0; p < 8; p++) { az[p] = 0; ar[p] = 0; }
            {
                const float4* WA = g_WA + l * (HH * HH);
                const int ke = (kseg + 1) << 6;
#pragma unroll 2
                for (int k = kseg << 6; k < ke; k += 4) {
                    float4 w0 = __ldcg(WA + (k+0) * HH + C);
                    float4 w1 = __ldcg(WA + (k+1) * HH + C);
                    float4 w2 = __ldcg(WA + (k+2) * HH + C);
                    float4 w3 = __ldcg(WA + (k+3) * HH + C);
                    ull xz0 = splat2(w0.x), hz0 = splat2(w0.y), xr0 = splat2(w0.z), hr0 = splat2(w0.w);
                    ull xz1 = splat2(w1.x), hz1 = splat2(w1.y), xr1 = splat2(w1.z), hr1 = splat2(w1.w);
                    ull xz2 = splat2(w2.x), hz2 = splat2(w2.y), xr2 = splat2(w2.z), hr2 = splat2(w2.w);
                    ull xz3 = splat2(w3.x), hz3 = splat2(w3.y), xr3 = splat2(w3.z), hr3 = splat2(w3.w);
#pragma unroll
                    for (int p = 0; p < 8; p++) {
                        ulonglong2 t01 = *(const ulonglong2*)(sh_t + p * HH + k);
                        ulonglong2 t23 = *(const ulonglong2*)(sh_t + p * HH + k + 2);
                        ulonglong2 h01 = *(const ulonglong2*)(sh_h + p * HH + k);
                        ulonglong2 h23 = *(const ulonglong2*)(sh_h + p * HH + k + 2);
                        fma2(az[p], t01.x, xz0); fma2(az[p], h01.x, hz0);
                        fma2(az[p], t01.y, xz1); fma2(az[p], h01.y, hz1);
                        fma2(az[p], t23.x, xz2); fma2(az[p], h23.x, hz2);
                        fma2(az[p], t23.y, xz3); fma2(az[p], h23.y, hz3);
                        fma2(ar[p], t01.x, xr0); fma2(ar[p], h01.x, hr0);
                        fma2(ar[p], t01.y, xr1); fma2(ar[p], h01.y, hr1);
                        fma2(ar[p], t23.x, xr2); fma2(ar[p], h23.x, hr2);
                        fma2(ar[p], t23.y, xr3); fma2(ar[p], h23.y, hr3);
                    }
                }
            }
            __syncthreads();
            // fold 16 k-segments into 8 slots, then flat 8-way gather
            if (kseg >= 8) {
                int sl = kseg - 8;
#pragma unroll
                for (int p = 0; p < 8; p++) {
                    red[(sl*16 +     p) * 32 + c] = az[p];
                    red[(sl*16 + 8 + p) * 32 + c] = ar[p];
                }
            }
            __syncthreads();
            if (kseg < 8) {
#pragma unroll
                for (int p = 0; p < 8; p++) {
                    red[(kseg*16 +     p)*32 + c] = add2(red[(kseg*16 +     p)*32 + c], az[p]);
                    red[(kseg*16 + 8 + p)*32 + c] = add2(red[(kseg*16 + 8 + p)*32 + c], ar[p]);
                }
            }
            __syncthreads();
            {
                int a = kseg;                      // array id 0..15 (0..7 = z, 8..15 = r)
                ull sum = red[a * 32 + c];
#pragma unroll
                for (int sl = 1; sl < 8; sl++)
                    sum = add2(sum, red[(sl*16 + a) * 32 + c]);
                float2 f = up2(sum);
                int Cg = C;
                if (a < 8) {
                    int p = a;
                    float bz = bhz[l * HH + Cg];
                    sh_z[p * 32 + c] = make_float2(1.f/(1.f+expf(-(f.x+bz))),
                                                   1.f/(1.f+expf(-(f.y+bz))));
                } else {
                    int p = a - 8;
                    float br = bhr[l * HH + Cg];
                    float r0 = 1.f/(1.f+expf(-(f.x+br)));
                    float r1 = 1.f/(1.f+expf(-(f.y+br)));
                    float2 hv = sh_h[p * HH + Cg];
                    g_rh[(P0+p) * HH + Cg] = make_float2(r0*hv.x, r1*hv.y);
                }
            }
            target += NBLK; gsync(target);

            // ======== phase B: g = t_in@Wxg + (r*h)@Whg, then update ========
            {
                const float2* rsrc = g_rh + P0 * HH;
                for (int i = tid; i < 4096; i += NTHR) {
                    int p  = i >> 9;
                    int k2 = (i & 511) << 1;
                    *(float4*)(sh_h + p * HH + k2) = __ldcg((const float4*)(rsrc + p * HH + k2));
                }
            }
            __syncthreads();
            ull ag[8];
#pragma unroll
            for (int p = 0; p < 8; p++) ag[p] = 0;
            {
                const float4* WX = g_WxG4 + l * ((HH/4) * HH);
                const float4* WH = g_WhG4 + l * ((HH/4) * HH);
                const int k4e = (kseg + 1) << 4;
#pragma unroll 2
                for (int k4 = kseg << 4; k4 < k4e; k4++) {
                    float4 wx = __ldcg(WX + k4 * HH + C);
                    float4 wh = __ldcg(WH + k4 * HH + C);
                    ull x0 = splat2(wx.x), x1 = splat2(wx.y), x2 = splat2(wx.z), x3 = splat2(wx.w);
                    ull h0 = splat2(wh.x), h1 = splat2(wh.y), h2 = splat2(wh.z), h3 = splat2(wh.w);
                    int k = k4 << 2;
#pragma unroll
                    for (int p = 0; p < 8; p++) {
                        ulonglong2 t01 = *(const ulonglong2*)(sh_t + p * HH + k);
                        ulonglong2 t23 = *(const ulonglong2*)(sh_t + p * HH + k + 2);
                        ulonglong2 r01 = *(const ulonglong2*)(sh_h + p * HH + k);
                        ulonglong2 r23 = *(const ulonglong2*)(sh_h + p * HH + k + 2);
                        fma2(ag[p], t01.x, x0); fma2(ag[p], r01.x, h0);
                        fma2(ag[p], t01.y, x1); fma2(ag[p], r01.y, h1);
                        fma2(ag[p], t23.x, x2); fma2(ag[p], r23.x, h2);
                        fma2(ag[p], t23.y, x3); fma2(ag[p], r23.y, h3);
                    }
                }
            }
            __syncthreads();
            if (kseg >= 8) {
                int sl = kseg - 8;
#pragma unroll
                for (int p = 0; p < 8; p++) red[(sl*8 + p)*32 + c] = ag[p];
            }
            __syncthreads();
            if (kseg < 8) {
#pragma unroll
                for (int p = 0; p < 8; p++)
                    red[(kseg*8 + p)*32 + c] = add2(red[(kseg*8 + p)*32 + c], ag[p]);
            }
            __syncthreads();
            if (tid < 256) {
                int p = tid >> 5, cc = tid & 31;
                int Cg = C0 + cc;
                ull sum = red[p * 32 + cc];
#pragma unroll
                for (int sl = 1; sl < 8; sl++)
                    sum = add2(sum, red[(sl*8 + p) * 32 + cc]);
                float2 f  = up2(sum);
                float bg  = bhg[l * HH + Cg];
                float g0 = tanhf(f.x + bg);
                float g1 = tanhf(f.y + bg);
                float2 zz = sh_z[p * 32 + cc];
                float2 hh = (l == 0) ? h0r : (l == 1) ? h1r : h2r;
                float hn0 = zz.x * hh.x + (1.f - zz.x) * g0;
                float hn1 = zz.y * hh.y + (1.f - zz.y) * g1;
                float2 hn = make_float2(hn0, hn1);
                if (l == 0) h0r = hn; else if (l == 1) h1r = hn; else h2r = hn;
                g_h[(l * NPAIR + P0 + p) * HH + Cg] = hn;
                if (l == 2)
                    g_h2[((long)s * NPAIR + P0 + p) * HH + Cg] = hn;
            }
            target += NBLK; gsync(target);
        }
    }
}

// ---------------- hidden-state output (B, L, H) ----------------
__global__ void copy_hidden(float* __restrict__ out2) {
    int idx = blockIdx.x * blockDim.x + threadIdx.x;
    if (idx >= LL * 64 * HH) return;
    int k = idx & 1023, b = (idx >> 10) & 63, l = idx >> 16;
    float2 v = g_h[(l * NPAIR + (b >> 1)) * HH + k];
    out2[(b * LL + l) * HH + k] = (b & 1) ? v.y : v.x;
}

// ---------------- output projection ----------------
// grid (8, 4096): 64 o-cols x 4 pair-rows per block; 256 threads = 64 o x 4 row-slots.
__global__ void __launch_bounds__(256) outGemm(const float* __restrict__ bo, float* __restrict__ out) {
    __shared__ __align__(16) float2 sh[4 * HH];
    int tid   = threadIdx.x;
    int o     = blockIdx.x * 64 + (tid & 63);
    int rslot = tid >> 6;
    long r0   = (long)blockIdx.y * 4;

    for (int i = tid; i < 2048; i += 256) {
        int rr = i >> 9;
        int k2 = (i & 511) << 1;
        *(float4*)(sh + rr * HH + k2) = *(const float4*)(g_h2 + (r0 + rr) * HH + k2);
    }
    __syncthreads();

    ull acc = 0;
    const float2* row = sh + rslot * HH;
    for (int k4 = 0; k4 < 256; k4++) {
        float4 w = g_WO4[k4 * OO + o];
        ull s0 = splat2(w.x), s1 = splat2(w.y), s2 = splat2(w.z), s3 = splat2(w.w);
        int k = k4 << 2;
        ulonglong2 t01 = *(const ulonglong2*)(row + k);
        ulonglong2 t23 = *(const ulonglong2*)(row + k + 2);
        fma2(acc, t01.x, s0); fma2(acc, t01.y, s1);
        fma2(acc, t23.x, s2); fma2(acc, t23.y, s3);
    }
    float2 f = up2(acc);
    long pr  = r0 + rslot;
    int sidx = (int)(pr >> 5);
    int p    = (int)(pr & 31);
    float bv = bo[o];
    out[((long)(2*p)     * SS + sidx) * OO + o] = f.x + bv;
    out[((long)(2*p + 1) * SS + sidx) * OO + o] = f.y + bv;
}

// ---------------- launch (7 graph nodes) ----------------
extern "C" void kernel_launch(void* const* d_in, const int* in_sizes, int n_in,
                              void* d_out, int out_size) {
    const float* x   = (const float*)d_in[0];
    const float* h0  = (const float*)d_in[1];
    const float* Wxz = (const float*)d_in[2];
    const float* Wxr = (const float*)d_in[3];
    const float* Wxg = (const float*)d_in[4];
    const float* Whz = (const float*)d_in[5];
    const float* Whr = (const float*)d_in[6];
    const float* Whg = (const float*)d_in[7];
    const float* bhz = (const float*)d_in[8];
    const float* bhr = (const float*)d_in[9];
    const float* bhg = (const float*)d_in[10];
    const float* Wo  = (const float*)d_in[11];
    const float* bo  = (const float*)d_in[12];
    float* out = (float*)d_out;

    static int smem_set = 0;
    if (!smem_set) {
        cudaFuncSetAttribute(gru_persist, cudaFuncAttributeMaxDynamicSharedMemorySize, SMEM_BYTES);
        smem_set = 1;
    }

    pack_main<<<(LL * HH * HH + 255) / 256, 256>>>(Wxz, Whz, Wxr, Whr);
    pack_g4  <<<(LL * (HH/4) * HH + 255) / 256, 256>>>(Wxg, Whg);
    pack_o   <<<((HH/4) * OO + 255) / 256, 256>>>(Wo);
    init_h   <<<(LL * NPAIR * HH + 255) / 256, 256>>>(h0);

    gru_persist<<<NBLK, NTHR, SMEM_BYTES>>>(x, bhz, bhr, bhg);

    copy_hidden<<<(LL * 64 * HH + 255) / 256, 256>>>(out + (long)64 * SS * OO);
    outGemm<<<dim3(8, (SS * NPAIR) / 4), 256>>>(bo, out);
}